// round 10
// baseline (speedup 1.0000x reference)
#include <cuda_runtime.h>
#include <cuda_fp16.h>
#include <math.h>
#include <stdint.h>

#define NMAX      500000
#define DIM       128
#define SNEG      256
#define STRIDE    136          // fp16 units -> 272B row stride (data 256B + 16B pad)
#define MTILE     256          // rows per block
#define INV_T     10.0f
#define LOG_S     5.545177444479562f    // log(256)
#define BSCALE    1.4426950408889634f   // log2(e) only (fp16-safe accum magnitudes)
#define MAXBLOCKS 4096

__device__ __half    g_Qn[(size_t)NMAX * DIM];
__device__ float     g_partial[MAXBLOCKS];
__device__ unsigned  g_done;

// ---------------------------------------------------------------------------
__global__ void normalize_kernel(const float* __restrict__ E, int n) {
    int row  = (int)((blockIdx.x * (long long)blockDim.x + threadIdx.x) >> 5);
    int lane = threadIdx.x & 31;
    if (row >= n) return;
    float4 v = reinterpret_cast<const float4*>(E + (size_t)row * DIM)[lane];
    float ss = v.x * v.x + v.y * v.y + v.z * v.z + v.w * v.w;
#pragma unroll
    for (int o = 16; o > 0; o >>= 1) ss += __shfl_xor_sync(0xffffffffu, ss, o);
    float inv = 1.0f / fmaxf(sqrtf(ss), 1e-12f);
    __half2 p0 = __floats2half2_rn(v.x * inv, v.y * inv);
    __half2 p1 = __floats2half2_rn(v.z * inv, v.w * inv);
    uint2 st;
    st.x = reinterpret_cast<unsigned&>(p0);
    st.y = reinterpret_cast<unsigned&>(p1);
    reinterpret_cast<uint2*>(g_Qn + (size_t)row * DIM)[lane] = st;
}

__device__ __forceinline__ float pairdot(unsigned a, unsigned b) {
    float2 fa = __half22float2(*reinterpret_cast<__half2*>(&a));
    float2 fb = __half22float2(*reinterpret_cast<__half2*>(&b));
    return fa.x * fb.x + fa.y * fb.y;
}

__device__ __forceinline__ uint32_t smem_u32(const void* p) {
    uint32_t a;
    asm("{ .reg .u64 t; cvta.to.shared.u64 t, %1; cvt.u32.u64 %0, t; }"
        : "=r"(a) : "l"(p));
    return a;
}

__device__ __forceinline__ float ex2f(float x) {
    float y;
    asm("ex2.approx.ftz.f32 %0, %1;" : "=f"(y) : "f"(x));
    return y;
}

// ---------------------------------------------------------------------------
// main: per 256-row tile, coalesced gathers + fp16-acc MMA (A hoisted LDG,
// B via ldmatrix) + fused logsumexp; last block folds the final reduction.
// ---------------------------------------------------------------------------
__global__ __launch_bounds__(256, 2) void main_kernel(
    const void* __restrict__ pos_idx,
    const void* __restrict__ neg_idx,
    float* __restrict__ out,
    int n, int nblocks)
{
    extern __shared__ char smem_raw[];
    __half* sV  = reinterpret_cast<__half*>(smem_raw);          // 256*136 fp16
    float* sPos = reinterpret_cast<float*>(sV + SNEG * STRIDE); // 256 floats
    float* sRed = sPos + MTILE;                                  // 8 floats
    int*   sLastP = reinterpret_cast<int*>(sRed + 8);

    const int tid  = threadIdx.x;
    const int lane = tid & 31;
    const int warp = tid >> 5;
    const long long tile0 = (long long)blockIdx.x * MTILE;

    // ---- inline index-dtype detection (first 1KB of negatives) -------------
    int ok = 1;
    if (tid < 128) {
        long long v = ((const long long*)neg_idx)[tid];
        ok = (v >= 0 && v < (long long)n);
    }
    const int is64 = __syncthreads_and(ok);

    const int half16 = lane & 15;    // lane within 16-lane row group
    const int rsel   = lane >> 4;    // which of 2 rows this iteration

    // ---- stage 256 negatives, coalesced: 16 lanes x uint4 per row, ---------
    // ---- 2 rows per instruction, pre-scaled by log2(e) ----------------------
    {
        const __half2 sc = __float2half2_rn(BSCALE);
#pragma unroll
        for (int i = 0; i < 16; i++) {
            int r = warp * 32 + 2 * i + rsel;
            long long vr = is64 ? ((const long long*)neg_idx)[r]
                                : (long long)((const int*)neg_idx)[r];
            uint4 v = *reinterpret_cast<const uint4*>(
                g_Qn + (size_t)vr * DIM + half16 * 8);
            __half2* h = reinterpret_cast<__half2*>(&v);
            h[0] = __hmul2(h[0], sc);
            h[1] = __hmul2(h[1], sc);
            h[2] = __hmul2(h[2], sc);
            h[3] = __hmul2(h[3], sc);
            *reinterpret_cast<uint4*>(sV + r * STRIDE + half16 * 8) = v;
        }
    }

    // ---- positive logits, coalesced: 16 lanes per row, 2 rows/iter ---------
    {
#pragma unroll
        for (int i = 0; i < 16; i++) {
            int rloc = warp * 32 + 2 * i + rsel;
            long long row = tile0 + rloc;
            float d = 0.0f;
            if (row < n) {
                long long p = is64 ? ((const long long*)pos_idx)[row]
                                   : (long long)((const int*)pos_idx)[row];
                uint4 a = *reinterpret_cast<const uint4*>(
                    g_Qn + (size_t)row * DIM + half16 * 8);
                uint4 b = *reinterpret_cast<const uint4*>(
                    g_Qn + (size_t)p * DIM + half16 * 8);
                d = pairdot(a.x, b.x) + pairdot(a.y, b.y)
                  + pairdot(a.z, b.z) + pairdot(a.w, b.w);
            }
#pragma unroll
            for (int o = 8; o > 0; o >>= 1)
                d += __shfl_xor_sync(0xffffffffu, d, o);
            if (half16 == 0) sPos[rloc] = d * INV_T;
        }
    }
    __syncthreads();

    // ---- GEMM: warp = 32 rows (2 T-tiles) x 256 negs ----
    const int g  = lane >> 2;
    const int t4 = lane & 3;
    const long long rowG = tile0 + warp * 32 + g;

    // hoist ALL A fragments (loaded once per tile, reused by all 4 chunks)
    unsigned afr[2][8][4];
#pragma unroll
    for (int T = 0; T < 2; T++) {
        long long r0 = rowG + T * 16;
        long long r1 = r0 + 8;
        const bool v0 = r0 < n, v1 = r1 < n;
        const unsigned* p0 = reinterpret_cast<const unsigned*>(
            g_Qn + (size_t)r0 * DIM + 2 * t4);
        const unsigned* p1 = reinterpret_cast<const unsigned*>(
            g_Qn + (size_t)r1 * DIM + 2 * t4);
#pragma unroll
        for (int k0 = 0; k0 < 8; k0++) {
            afr[T][k0][0] = v0 ? p0[k0 * 8]     : 0u;
            afr[T][k0][1] = v1 ? p1[k0 * 8]     : 0u;
            afr[T][k0][2] = v0 ? p0[k0 * 8 + 4] : 0u;
            afr[T][k0][3] = v1 ? p1[k0 * 8 + 4] : 0u;
        }
    }

    // ldmatrix lane->row map: lanes 0-7: n 0-7 (k lo) | 8-15: n 0-7 (k hi)
    //                         lanes 16-23: n 8-15 (k lo) | 24-31: n 8-15 (k hi)
    const int nrow = (lane & 7) + ((lane & 16) >> 1);
    const uint32_t bAddr = smem_u32(sV) + nrow * (STRIDE * 2)
                         + ((lane & 8) << 1);

    float rs[2][2] = {{0.f, 0.f}, {0.f, 0.f}};

#pragma unroll
    for (int c = 0; c < 4; c++) {
        unsigned acc[2][8][2];
#pragma unroll
        for (int T = 0; T < 2; T++)
#pragma unroll
            for (int i = 0; i < 8; i++) { acc[T][i][0] = 0u; acc[T][i][1] = 0u; }

#pragma unroll
        for (int k0 = 0; k0 < 8; k0++) {
#pragma unroll
            for (int nt2 = 0; nt2 < 4; nt2++) {
                unsigned b0, b1, b2, b3;
                uint32_t a = bAddr + (c * 64 + nt2 * 16) * (STRIDE * 2) + k0 * 32;
                asm volatile(
                    "ldmatrix.sync.aligned.m8n8.x4.shared.b16 "
                    "{%0,%1,%2,%3}, [%4];"
                    : "=r"(b0), "=r"(b1), "=r"(b2), "=r"(b3) : "r"(a));
#pragma unroll
                for (int T = 0; T < 2; T++) {
                    asm volatile(
                        "mma.sync.aligned.m16n8k16.row.col.f16.f16.f16.f16 "
                        "{%0,%1}, {%2,%3,%4,%5}, {%6,%7}, {%0,%1};\n"
                        : "+r"(acc[T][nt2 * 2][0]), "+r"(acc[T][nt2 * 2][1])
                        : "r"(afr[T][k0][0]), "r"(afr[T][k0][1]),
                          "r"(afr[T][k0][2]), "r"(afr[T][k0][3]),
                          "r"(b0), "r"(b1));
                    asm volatile(
                        "mma.sync.aligned.m16n8k16.row.col.f16.f16.f16.f16 "
                        "{%0,%1}, {%2,%3,%4,%5}, {%6,%7}, {%0,%1};\n"
                        : "+r"(acc[T][nt2 * 2 + 1][0]), "+r"(acc[T][nt2 * 2 + 1][1])
                        : "r"(afr[T][k0][0]), "r"(afr[T][k0][1]),
                          "r"(afr[T][k0][2]), "r"(afr[T][k0][3]),
                          "r"(b2), "r"(b3));
                }
            }
        }
        // ---- epilogue: acc holds dot*log2e -> ex2(acc*10) ----
#pragma unroll
        for (int T = 0; T < 2; T++)
#pragma unroll
            for (int nt = 0; nt < 8; nt++) {
                float2 lo = __half22float2(
                    *reinterpret_cast<__half2*>(&acc[T][nt][0]));
                float2 hi = __half22float2(
                    *reinterpret_cast<__half2*>(&acc[T][nt][1]));
                rs[T][0] += ex2f(lo.x * INV_T) + ex2f(lo.y * INV_T);
                rs[T][1] += ex2f(hi.x * INV_T) + ex2f(hi.y * INV_T);
            }
    }

    // reduce exp-sums across the 4 lanes of each row group
#pragma unroll
    for (int T = 0; T < 2; T++) {
        rs[T][0] += __shfl_xor_sync(0xffffffffu, rs[T][0], 1);
        rs[T][0] += __shfl_xor_sync(0xffffffffu, rs[T][0], 2);
        rs[T][1] += __shfl_xor_sync(0xffffffffu, rs[T][1], 1);
        rs[T][1] += __shfl_xor_sync(0xffffffffu, rs[T][1], 2);
    }

    float contrib = 0.0f;
    if (t4 == 0) {
#pragma unroll
        for (int T = 0; T < 2; T++) {
            long long r0 = rowG + T * 16;
            if (r0 < n)
                contrib += sPos[warp * 32 + T * 16 + g]
                         - (logf(rs[T][0]) - LOG_S);
            if (r0 + 8 < n)
                contrib += sPos[warp * 32 + T * 16 + g + 8]
                         - (logf(rs[T][1]) - LOG_S);
        }
    }
#pragma unroll
    for (int o = 16; o > 0; o >>= 1)
        contrib += __shfl_xor_sync(0xffffffffu, contrib, o);
    if (lane == 0) sRed[warp] = contrib;
    __syncthreads();

    // ---- publish partial; last block does the deterministic final sum ------
    if (tid == 0) {
        float s = 0.0f;
#pragma unroll
        for (int w = 0; w < 8; w++) s += sRed[w];
        g_partial[blockIdx.x] = s;
        __threadfence();
        unsigned t = atomicAdd(&g_done, 1u);
        *sLastP = (t == (unsigned)(nblocks - 1));
    }
    __syncthreads();
    if (*sLastP) {
        float s = 0.0f;
        for (int i = tid; i < nblocks; i += 256) s += g_partial[i];
        __syncthreads();
        sPos[tid] = s;
        __syncthreads();
        for (int o = 128; o > 0; o >>= 1) {
            if (tid < o) sPos[tid] += sPos[tid + o];
            __syncthreads();
        }
        if (tid == 0) {
            out[0] = -sPos[0] / (float)n;
            g_done = 0;                  // reset for next graph replay
        }
    }
}

// ---------------------------------------------------------------------------
extern "C" void kernel_launch(void* const* d_in, const int* in_sizes, int n_in,
                              void* d_out, int out_size) {
    const float* E   = (const float*)d_in[0];
    const void*  pos = d_in[1];
    const void*  neg = d_in[2];
    int n = in_sizes[1];   // number of edges

    int nblk_norm = (n + 7) / 8;
    normalize_kernel<<<nblk_norm, 256>>>(E, n);

    int nblocks = (n + MTILE - 1) / MTILE;
    size_t smem = (size_t)(SNEG * STRIDE) * sizeof(__half)
                + (size_t)(MTILE + 8 + 4) * sizeof(float);
    cudaFuncSetAttribute(main_kernel,
                         cudaFuncAttributeMaxDynamicSharedMemorySize, (int)smem);
    main_kernel<<<nblocks, 256, smem>>>(pos, neg, (float*)d_out, n, nblocks);
}

// round 11
// speedup vs baseline: 1.0243x; 1.0243x over previous
#include <cuda_runtime.h>
#include <cuda_fp16.h>
#include <math.h>
#include <stdint.h>

#define NMAX      500000
#define DIM       128
#define SNEG      256
#define STRIDE    136          // fp16 units -> 272B row stride (data 256B + 16B pad)
#define MTILE     128          // rows per block
#define INV_T     10.0f
#define LOG_S     5.545177444479562f    // log(256)
#define BSCALE    1.4426950408889634f   // log2(e) folded into staged B
#define MAXBLOCKS 8192

__device__ __half    g_Qn[(size_t)NMAX * DIM];
__device__ float     g_partial[MAXBLOCKS];
__device__ unsigned  g_done;

// ---------------------------------------------------------------------------
__global__ void normalize_kernel(const float* __restrict__ E, int n) {
    int row  = (int)((blockIdx.x * (long long)blockDim.x + threadIdx.x) >> 5);
    int lane = threadIdx.x & 31;
    if (row >= n) return;
    float4 v = reinterpret_cast<const float4*>(E + (size_t)row * DIM)[lane];
    float ss = v.x * v.x + v.y * v.y + v.z * v.z + v.w * v.w;
#pragma unroll
    for (int o = 16; o > 0; o >>= 1) ss += __shfl_xor_sync(0xffffffffu, ss, o);
    float inv = 1.0f / fmaxf(sqrtf(ss), 1e-12f);
    __half2 p0 = __floats2half2_rn(v.x * inv, v.y * inv);
    __half2 p1 = __floats2half2_rn(v.z * inv, v.w * inv);
    uint2 st;
    st.x = reinterpret_cast<unsigned&>(p0);
    st.y = reinterpret_cast<unsigned&>(p1);
    reinterpret_cast<uint2*>(g_Qn + (size_t)row * DIM)[lane] = st;
}

__device__ __forceinline__ float pairdot(unsigned a, unsigned b) {
    float2 fa = __half22float2(*reinterpret_cast<__half2*>(&a));
    float2 fb = __half22float2(*reinterpret_cast<__half2*>(&b));
    return fa.x * fb.x + fa.y * fb.y;
}

__device__ __forceinline__ uint32_t smem_u32(const void* p) {
    uint32_t a;
    asm("{ .reg .u64 t; cvta.to.shared.u64 t, %1; cvt.u32.u64 %0, t; }"
        : "=r"(a) : "l"(p));
    return a;
}

__device__ __forceinline__ float ex2f(float x) {
    float y;
    asm("ex2.approx.ftz.f32 %0, %1;" : "=f"(y) : "f"(x));
    return y;
}

// ---------------------------------------------------------------------------
// main: per 128-row tile, coalesced gathers + f32-acc MMA (A hoisted, B via
// ldmatrix, 32-neg chunks) + fused logsumexp; last block folds the reduction.
// 3 CTAs/SM target.
// ---------------------------------------------------------------------------
__global__ __launch_bounds__(256, 3) void main_kernel(
    const void* __restrict__ pos_idx,
    const void* __restrict__ neg_idx,
    float* __restrict__ out,
    int n, int nblocks)
{
    extern __shared__ char smem_raw[];
    __half* sV  = reinterpret_cast<__half*>(smem_raw);          // 256*136 fp16
    float* sPos = reinterpret_cast<float*>(sV + SNEG * STRIDE); // 128 floats
    float* sRed = sPos + MTILE;                                  // 8 floats
    int*   sLastP = reinterpret_cast<int*>(sRed + 8);

    const int tid  = threadIdx.x;
    const int lane = tid & 31;
    const int warp = tid >> 5;
    const long long tile0 = (long long)blockIdx.x * MTILE;

    // ---- inline index-dtype detection (first 1KB of negatives) -------------
    int ok = 1;
    if (tid < 128) {
        long long v = ((const long long*)neg_idx)[tid];
        ok = (v >= 0 && v < (long long)n);
    }
    const int is64 = __syncthreads_and(ok);

    const int half16 = lane & 15;    // lane within 16-lane row group
    const int rsel   = lane >> 4;    // which of 2 rows per iteration

    // ---- stage 256 negatives, coalesced (16 lanes x uint4/row, 2 rows/iter),
    // ---- pre-scaled by log2(e) ----------------------------------------------
    {
        const __half2 sc = __float2half2_rn(BSCALE);
#pragma unroll
        for (int i = 0; i < 16; i++) {
            int r = warp * 32 + 2 * i + rsel;
            long long vr = is64 ? ((const long long*)neg_idx)[r]
                                : (long long)((const int*)neg_idx)[r];
            uint4 v = *reinterpret_cast<const uint4*>(
                g_Qn + (size_t)vr * DIM + half16 * 8);
            __half2* h = reinterpret_cast<__half2*>(&v);
            h[0] = __hmul2(h[0], sc);
            h[1] = __hmul2(h[1], sc);
            h[2] = __hmul2(h[2], sc);
            h[3] = __hmul2(h[3], sc);
            *reinterpret_cast<uint4*>(sV + r * STRIDE + half16 * 8) = v;
        }
    }

    // ---- positive logits, coalesced: 16 lanes/row, 2 rows/iter (128 rows) --
    {
#pragma unroll
        for (int i = 0; i < 8; i++) {
            int rloc = warp * 16 + 2 * i + rsel;
            long long row = tile0 + rloc;
            float d = 0.0f;
            if (row < n) {
                long long p = is64 ? ((const long long*)pos_idx)[row]
                                   : (long long)((const int*)pos_idx)[row];
                uint4 a = *reinterpret_cast<const uint4*>(
                    g_Qn + (size_t)row * DIM + half16 * 8);
                uint4 b = *reinterpret_cast<const uint4*>(
                    g_Qn + (size_t)p * DIM + half16 * 8);
                d = pairdot(a.x, b.x) + pairdot(a.y, b.y)
                  + pairdot(a.z, b.z) + pairdot(a.w, b.w);
            }
#pragma unroll
            for (int o = 8; o > 0; o >>= 1)
                d += __shfl_xor_sync(0xffffffffu, d, o);
            if (half16 == 0) sPos[rloc] = d * INV_T;
        }
    }
    __syncthreads();

    // ---- GEMM: warp = 16 rows x 256 negs, 8 chunks of 32, f32 accum --------
    const int g  = lane >> 2;
    const int t4 = lane & 3;
    const long long rowG = tile0 + warp * 16 + g;

    // hoist A fragments once (32 regs)
    unsigned afr[8][4];
    {
        long long r0 = rowG;
        long long r1 = rowG + 8;
        const bool v0 = r0 < n, v1 = r1 < n;
        const unsigned* p0 = reinterpret_cast<const unsigned*>(
            g_Qn + (size_t)r0 * DIM + 2 * t4);
        const unsigned* p1 = reinterpret_cast<const unsigned*>(
            g_Qn + (size_t)r1 * DIM + 2 * t4);
#pragma unroll
        for (int k0 = 0; k0 < 8; k0++) {
            afr[k0][0] = v0 ? p0[k0 * 8]     : 0u;
            afr[k0][1] = v1 ? p1[k0 * 8]     : 0u;
            afr[k0][2] = v0 ? p0[k0 * 8 + 4] : 0u;
            afr[k0][3] = v1 ? p1[k0 * 8 + 4] : 0u;
        }
    }

    // ldmatrix lane->row map (x4: two n-tiles x k lo/hi)
    const int nrow = (lane & 7) + ((lane & 16) >> 1);
    const uint32_t bAddr = smem_u32(sV) + nrow * (STRIDE * 2)
                         + ((lane & 8) << 1);

    float rs0 = 0.0f, rs1 = 0.0f;     // exp-sums for row g and row g+8

#pragma unroll
    for (int c = 0; c < 8; c++) {     // 8 chunks of 32 negatives
        float acc[4][4];
#pragma unroll
        for (int i = 0; i < 4; i++) {
            acc[i][0] = 0.f; acc[i][1] = 0.f; acc[i][2] = 0.f; acc[i][3] = 0.f;
        }
#pragma unroll
        for (int k0 = 0; k0 < 8; k0++) {
#pragma unroll
            for (int nt2 = 0; nt2 < 2; nt2++) {
                unsigned b0, b1, b2, b3;
                uint32_t a = bAddr + (c * 32 + nt2 * 16) * (STRIDE * 2) + k0 * 32;
                asm volatile(
                    "ldmatrix.sync.aligned.m8n8.x4.shared.b16 "
                    "{%0,%1,%2,%3}, [%4];"
                    : "=r"(b0), "=r"(b1), "=r"(b2), "=r"(b3) : "r"(a));
                asm volatile(
                    "mma.sync.aligned.m16n8k16.row.col.f32.f16.f16.f32 "
                    "{%0,%1,%2,%3}, {%4,%5,%6,%7}, {%8,%9}, {%0,%1,%2,%3};\n"
                    : "+f"(acc[nt2 * 2][0]), "+f"(acc[nt2 * 2][1]),
                      "+f"(acc[nt2 * 2][2]), "+f"(acc[nt2 * 2][3])
                    : "r"(afr[k0][0]), "r"(afr[k0][1]),
                      "r"(afr[k0][2]), "r"(afr[k0][3]),
                      "r"(b0), "r"(b1));
                asm volatile(
                    "mma.sync.aligned.m16n8k16.row.col.f32.f16.f16.f32 "
                    "{%0,%1,%2,%3}, {%4,%5,%6,%7}, {%8,%9}, {%0,%1,%2,%3};\n"
                    : "+f"(acc[nt2 * 2 + 1][0]), "+f"(acc[nt2 * 2 + 1][1]),
                      "+f"(acc[nt2 * 2 + 1][2]), "+f"(acc[nt2 * 2 + 1][3])
                    : "r"(afr[k0][0]), "r"(afr[k0][1]),
                      "r"(afr[k0][2]), "r"(afr[k0][3]),
                      "r"(b2), "r"(b3));
            }
        }
        // ---- epilogue: acc holds dot*log2e (f32) -> ex2(acc*10) ----
#pragma unroll
        for (int nt = 0; nt < 4; nt++) {
            rs0 += ex2f(acc[nt][0] * INV_T) + ex2f(acc[nt][1] * INV_T);
            rs1 += ex2f(acc[nt][2] * INV_T) + ex2f(acc[nt][3] * INV_T);
        }
    }

    // reduce exp-sums across the 4 lanes of each row group
    rs0 += __shfl_xor_sync(0xffffffffu, rs0, 1);
    rs0 += __shfl_xor_sync(0xffffffffu, rs0, 2);
    rs1 += __shfl_xor_sync(0xffffffffu, rs1, 1);
    rs1 += __shfl_xor_sync(0xffffffffu, rs1, 2);

    float contrib = 0.0f;
    if (t4 == 0) {
        if (rowG < n)
            contrib += sPos[warp * 16 + g]     - (logf(rs0) - LOG_S);
        if (rowG + 8 < n)
            contrib += sPos[warp * 16 + g + 8] - (logf(rs1) - LOG_S);
    }
#pragma unroll
    for (int o = 16; o > 0; o >>= 1)
        contrib += __shfl_xor_sync(0xffffffffu, contrib, o);
    if (lane == 0) sRed[warp] = contrib;
    __syncthreads();

    // ---- publish partial; last block does the deterministic final sum ------
    if (tid == 0) {
        float s = 0.0f;
#pragma unroll
        for (int w = 0; w < 8; w++) s += sRed[w];
        g_partial[blockIdx.x] = s;
        __threadfence();
        unsigned t = atomicAdd(&g_done, 1u);
        *sLastP = (t == (unsigned)(nblocks - 1));
    }
    __syncthreads();
    if (*sLastP) {
        float s = 0.0f;
        for (int i = tid; i < nblocks; i += 256) s += g_partial[i];
        __syncthreads();
        sPos[tid & 127] = 0.f;           // (unused lanes cleared below anyway)
        __syncthreads();
        // block tree over 256 partial-sums held in registers via shfl first
#pragma unroll
        for (int o = 16; o > 0; o >>= 1)
            s += __shfl_xor_sync(0xffffffffu, s, o);
        if (lane == 0) sRed[warp] = s;
        __syncthreads();
        if (tid == 0) {
            float tot = 0.f;
#pragma unroll
            for (int w = 0; w < 8; w++) tot += sRed[w];
            out[0] = -tot / (float)n;
            g_done = 0;                  // reset for next graph replay
        }
    }
}

// ---------------------------------------------------------------------------
extern "C" void kernel_launch(void* const* d_in, const int* in_sizes, int n_in,
                              void* d_out, int out_size) {
    const float* E   = (const float*)d_in[0];
    const void*  pos = d_in[1];
    const void*  neg = d_in[2];
    int n = in_sizes[1];   // number of edges

    int nblk_norm = (n + 7) / 8;
    normalize_kernel<<<nblk_norm, 256>>>(E, n);

    int nblocks = (n + MTILE - 1) / MTILE;
    size_t smem = (size_t)(SNEG * STRIDE) * sizeof(__half)
                + (size_t)(MTILE + 8 + 4) * sizeof(float);
    cudaFuncSetAttribute(main_kernel,
                         cudaFuncAttributeMaxDynamicSharedMemorySize, (int)smem);
    main_kernel<<<nblocks, 256, smem>>>(pos, neg, (float*)d_out, n, nblocks);
}

// round 12
// speedup vs baseline: 1.1598x; 1.1323x over previous
#include <cuda_runtime.h>
#include <cuda_fp16.h>
#include <math.h>
#include <stdint.h>

#define NMAX      500000
#define DIM       128
#define SNEG      256
#define STRIDE    136          // fp16 units -> 272B row stride (data 256B + 16B pad)
#define MTILE     128          // rows per tile
#define INV_T     10.0f
#define LOG_S     5.545177444479562f    // log(256)
#define EXSCALE   14.426950408889634f   // INV_T * log2(e), applied in f32 epilogue
#define GRIDP     444                   // persistent blocks (3 per SM)
#define MAXBLOCKS 8192

__device__ __half    g_Qn[(size_t)NMAX * DIM];
__device__ float     g_partial[MAXBLOCKS];
__device__ unsigned  g_done;

// ---------------------------------------------------------------------------
__global__ void normalize_kernel(const float* __restrict__ E, int n) {
    int row  = (int)((blockIdx.x * (long long)blockDim.x + threadIdx.x) >> 5);
    int lane = threadIdx.x & 31;
    if (row >= n) return;
    float4 v = reinterpret_cast<const float4*>(E + (size_t)row * DIM)[lane];
    float ss = v.x * v.x + v.y * v.y + v.z * v.z + v.w * v.w;
#pragma unroll
    for (int o = 16; o > 0; o >>= 1) ss += __shfl_xor_sync(0xffffffffu, ss, o);
    float inv = 1.0f / fmaxf(sqrtf(ss), 1e-12f);
    __half2 p0 = __floats2half2_rn(v.x * inv, v.y * inv);
    __half2 p1 = __floats2half2_rn(v.z * inv, v.w * inv);
    uint2 st;
    st.x = reinterpret_cast<unsigned&>(p0);
    st.y = reinterpret_cast<unsigned&>(p1);
    reinterpret_cast<uint2*>(g_Qn + (size_t)row * DIM)[lane] = st;
}

__device__ __forceinline__ float pairdot(unsigned a, unsigned b) {
    float2 fa = __half22float2(*reinterpret_cast<__half2*>(&a));
    float2 fb = __half22float2(*reinterpret_cast<__half2*>(&b));
    return fa.x * fb.x + fa.y * fb.y;
}

__device__ __forceinline__ uint32_t smem_u32(const void* p) {
    uint32_t a;
    asm("{ .reg .u64 t; cvta.to.shared.u64 t, %1; cvt.u32.u64 %0, t; }"
        : "=r"(a) : "l"(p));
    return a;
}

__device__ __forceinline__ float ex2f(float x) {
    float y;
    asm("ex2.approx.ftz.f32 %0, %1;" : "=f"(y) : "f"(x));
    return y;
}

// ---------------------------------------------------------------------------
// main: persistent blocks; B staged once per block; per tile each warp owns
// its 16 rows end-to-end (pos-dot, A fragments, GEMM, lse) -> no block
// barriers in the tile loop. f32 accum, scale applied in epilogue.
// ---------------------------------------------------------------------------
__global__ __launch_bounds__(256, 3) void main_kernel(
    const void* __restrict__ pos_idx,
    const void* __restrict__ neg_idx,
    float* __restrict__ out,
    int n, int ntiles)
{
    extern __shared__ char smem_raw[];
    __half* sV  = reinterpret_cast<__half*>(smem_raw);          // 256*136 fp16
    float* sPos = reinterpret_cast<float*>(sV + SNEG * STRIDE); // 128 floats
    float* sRed = sPos + MTILE;                                  // 8 floats
    int*   sLastP = reinterpret_cast<int*>(sRed + 8);

    const int tid  = threadIdx.x;
    const int lane = tid & 31;
    const int warp = tid >> 5;

    // ---- inline index-dtype detection (first 1KB of negatives) -------------
    int ok = 1;
    if (tid < 128) {
        long long v = ((const long long*)neg_idx)[tid];
        ok = (v >= 0 && v < (long long)n);
    }
    const int is64 = __syncthreads_and(ok);

    const int half16 = lane & 15;
    const int rsel   = lane >> 4;

    // ---- stage 256 negatives ONCE, coalesced, unscaled ----------------------
    {
#pragma unroll
        for (int i = 0; i < 16; i++) {
            int r = warp * 32 + 2 * i + rsel;
            long long vr = is64 ? ((const long long*)neg_idx)[r]
                                : (long long)((const int*)neg_idx)[r];
            uint4 v = *reinterpret_cast<const uint4*>(
                g_Qn + (size_t)vr * DIM + half16 * 8);
            *reinterpret_cast<uint4*>(sV + r * STRIDE + half16 * 8) = v;
        }
    }
    __syncthreads();

    // ldmatrix lane->row map (x4: two n-tiles x k lo/hi)
    const int nrow = (lane & 7) + ((lane & 16) >> 1);
    const uint32_t bAddr = smem_u32(sV) + nrow * (STRIDE * 2)
                         + ((lane & 8) << 1);

    const int g  = lane >> 2;
    const int t4 = lane & 3;

    float local = 0.0f;

    for (int tile = blockIdx.x; tile < ntiles; tile += GRIDP) {
        const long long tile0 = (long long)tile * MTILE;

        // ---- positive logits for this warp's 16 rows (coalesced) -----------
#pragma unroll
        for (int i = 0; i < 8; i++) {
            int rloc = warp * 16 + 2 * i + rsel;
            long long row = tile0 + rloc;
            float d = 0.0f;
            if (row < n) {
                long long p = is64 ? ((const long long*)pos_idx)[row]
                                   : (long long)((const int*)pos_idx)[row];
                uint4 a = *reinterpret_cast<const uint4*>(
                    g_Qn + (size_t)row * DIM + half16 * 8);
                uint4 b = *reinterpret_cast<const uint4*>(
                    g_Qn + (size_t)p * DIM + half16 * 8);
                d = pairdot(a.x, b.x) + pairdot(a.y, b.y)
                  + pairdot(a.z, b.z) + pairdot(a.w, b.w);
            }
#pragma unroll
            for (int o = 8; o > 0; o >>= 1)
                d += __shfl_xor_sync(0xffffffffu, d, o);
            if (half16 == 0) sPos[rloc] = d * INV_T;
        }
        __syncwarp();   // sPos produced and consumed within this warp only

        // ---- A fragments for this warp's 16 rows ----------------------------
        const long long rowG = tile0 + warp * 16 + g;
        unsigned afr[8][4];
        {
            long long r0 = rowG, r1 = rowG + 8;
            const bool v0 = r0 < n, v1 = r1 < n;
            const unsigned* p0 = reinterpret_cast<const unsigned*>(
                g_Qn + (size_t)r0 * DIM + 2 * t4);
            const unsigned* p1 = reinterpret_cast<const unsigned*>(
                g_Qn + (size_t)r1 * DIM + 2 * t4);
#pragma unroll
            for (int k0 = 0; k0 < 8; k0++) {
                afr[k0][0] = v0 ? p0[k0 * 8]     : 0u;
                afr[k0][1] = v1 ? p1[k0 * 8]     : 0u;
                afr[k0][2] = v0 ? p0[k0 * 8 + 4] : 0u;
                afr[k0][3] = v1 ? p1[k0 * 8 + 4] : 0u;
            }
        }

        // ---- GEMM: 8 chunks of 32 negatives, f32 accum ----------------------
        float rs0 = 0.0f, rs1 = 0.0f;
#pragma unroll
        for (int c = 0; c < 8; c++) {
            float acc[4][4];
#pragma unroll
            for (int i = 0; i < 4; i++) {
                acc[i][0] = 0.f; acc[i][1] = 0.f;
                acc[i][2] = 0.f; acc[i][3] = 0.f;
            }
#pragma unroll
            for (int k0 = 0; k0 < 8; k0++) {
#pragma unroll
                for (int nt2 = 0; nt2 < 2; nt2++) {
                    unsigned b0, b1, b2, b3;
                    uint32_t a = bAddr + (c * 32 + nt2 * 16) * (STRIDE * 2)
                               + k0 * 32;
                    asm volatile(
                        "ldmatrix.sync.aligned.m8n8.x4.shared.b16 "
                        "{%0,%1,%2,%3}, [%4];"
                        : "=r"(b0), "=r"(b1), "=r"(b2), "=r"(b3) : "r"(a));
                    asm volatile(
                        "mma.sync.aligned.m16n8k16.row.col.f32.f16.f16.f32 "
                        "{%0,%1,%2,%3}, {%4,%5,%6,%7}, {%8,%9}, {%0,%1,%2,%3};\n"
                        : "+f"(acc[nt2 * 2][0]), "+f"(acc[nt2 * 2][1]),
                          "+f"(acc[nt2 * 2][2]), "+f"(acc[nt2 * 2][3])
                        : "r"(afr[k0][0]), "r"(afr[k0][1]),
                          "r"(afr[k0][2]), "r"(afr[k0][3]),
                          "r"(b0), "r"(b1));
                    asm volatile(
                        "mma.sync.aligned.m16n8k16.row.col.f32.f16.f16.f32 "
                        "{%0,%1,%2,%3}, {%4,%5,%6,%7}, {%8,%9}, {%0,%1,%2,%3};\n"
                        : "+f"(acc[nt2 * 2 + 1][0]), "+f"(acc[nt2 * 2 + 1][1]),
                          "+f"(acc[nt2 * 2 + 1][2]), "+f"(acc[nt2 * 2 + 1][3])
                        : "r"(afr[k0][0]), "r"(afr[k0][1]),
                          "r"(afr[k0][2]), "r"(afr[k0][3]),
                          "r"(b2), "r"(b3));
                }
            }
            // epilogue: logits = dot*10; exp via ex2(dot * 10*log2e)
#pragma unroll
            for (int nt = 0; nt < 4; nt++) {
                rs0 += ex2f(acc[nt][0] * EXSCALE) + ex2f(acc[nt][1] * EXSCALE);
                rs1 += ex2f(acc[nt][2] * EXSCALE) + ex2f(acc[nt][3] * EXSCALE);
            }
        }

        rs0 += __shfl_xor_sync(0xffffffffu, rs0, 1);
        rs0 += __shfl_xor_sync(0xffffffffu, rs0, 2);
        rs1 += __shfl_xor_sync(0xffffffffu, rs1, 1);
        rs1 += __shfl_xor_sync(0xffffffffu, rs1, 2);

        if (t4 == 0) {
            if (rowG < n)
                local += sPos[warp * 16 + g]     - (logf(rs0) - LOG_S);
            if (rowG + 8 < n)
                local += sPos[warp * 16 + g + 8] - (logf(rs1) - LOG_S);
        }
    }

    // ---- block reduction of per-thread sums (deterministic) ----------------
#pragma unroll
    for (int o = 16; o > 0; o >>= 1)
        local += __shfl_xor_sync(0xffffffffu, local, o);
    if (lane == 0) sRed[warp] = local;
    __syncthreads();

    if (tid == 0) {
        float s = 0.0f;
#pragma unroll
        for (int w = 0; w < 8; w++) s += sRed[w];
        g_partial[blockIdx.x] = s;
        __threadfence();
        unsigned t = atomicAdd(&g_done, 1u);
        *sLastP = (t == (unsigned)(GRIDP - 1));
    }
    __syncthreads();
    if (*sLastP) {
        float s = 0.0f;
        for (int i = tid; i < GRIDP; i += 256) s += g_partial[i];
#pragma unroll
        for (int o = 16; o > 0; o >>= 1)
            s += __shfl_xor_sync(0xffffffffu, s, o);
        if (lane == 0) sRed[warp] = s;
        __syncthreads();
        if (tid == 0) {
            float tot = 0.f;
#pragma unroll
            for (int w = 0; w < 8; w++) tot += sRed[w];
            out[0] = -tot / (float)n;
            g_done = 0;                  // reset for next graph replay
        }
    }
}

// ---------------------------------------------------------------------------
extern "C" void kernel_launch(void* const* d_in, const int* in_sizes, int n_in,
                              void* d_out, int out_size) {
    const float* E   = (const float*)d_in[0];
    const void*  pos = d_in[1];
    const void*  neg = d_in[2];
    int n = in_sizes[1];   // number of edges

    int nblk_norm = (n + 7) / 8;
    normalize_kernel<<<nblk_norm, 256>>>(E, n);

    int ntiles = (n + MTILE - 1) / MTILE;
    size_t smem = (size_t)(SNEG * STRIDE) * sizeof(__half)
                + (size_t)(MTILE + 8 + 4) * sizeof(float);
    cudaFuncSetAttribute(main_kernel,
                         cudaFuncAttributeMaxDynamicSharedMemorySize, (int)smem);
    main_kernel<<<GRIDP, 256, smem>>>(pos, neg, (float*)d_out, n, ntiles);
}